// round 10
// baseline (speedup 1.0000x reference)
#include <cuda_runtime.h>
#include <cstdint>

#define SEQ    512
#define BATCH  512
#define IN_DIM 128
#define NQ     8
#define D_TOT  136   // IN_DIM + NQ

#define NBLK       148   // == wave-1 capacity, all co-resident
#define ZX_BLOCKS  116
#define ZX_ROWS    128   // rows per tile
#define N_TILES    ((SEQ * BATCH) / ZX_ROWS)   // 2048; 4 tiles per step

// Scratch: Zx[s][b][o], o = g*8 + q
__device__ float g_zx[(size_t)SEQ * BATCH * 32];
__device__ int g_step_done[SEQ];
__device__ int g_frontier;
__device__ int g_ticket;

typedef unsigned long long ull;

// --- packed fp32x2 ops (Blackwell; PTX-only) ---
__device__ __forceinline__ ull fma2(ull a, ull b, ull c) {
    ull d; asm("fma.rn.f32x2 %0, %1, %2, %3;" : "=l"(d) : "l"(a), "l"(b), "l"(c)); return d;
}
__device__ __forceinline__ ull mul2(ull a, ull b) {
    ull d; asm("mul.rn.f32x2 %0, %1, %2;" : "=l"(d) : "l"(a), "l"(b)); return d;
}
__device__ __forceinline__ ull add2(ull a, ull b) {
    ull d; asm("add.rn.f32x2 %0, %1, %2;" : "=l"(d) : "l"(a), "l"(b)); return d;
}
__device__ __forceinline__ ull pack2(float lo, float hi) {
    ull d; asm("mov.b64 %0, {%1, %2};" : "=l"(d) : "r"(__float_as_uint(lo)), "r"(__float_as_uint(hi))); return d;
}
__device__ __forceinline__ void unpack2(ull v, float& lo, float& hi) {
    unsigned a, b; asm("mov.b64 {%0, %1}, %2;" : "=r"(a), "=r"(b) : "l"(v));
    lo = __uint_as_float(a); hi = __uint_as_float(b);
}
__device__ __forceinline__ ull dup2(float x) {
    ull d; unsigned u = __float_as_uint(x);
    asm("mov.b64 %0, {%1, %1};" : "=l"(d) : "r"(u)); return d;
}
__device__ __forceinline__ float rcp_fast(float x) {
    float r; asm("rcp.approx.f32 %0, %1;" : "=f"(r) : "f"(x)); return r;
}
__device__ __forceinline__ int ld_acquire(const int* p) {
    int v; asm volatile("ld.acquire.gpu.b32 %0, [%1];" : "=r"(v) : "l"(p)); return v;
}

// ============================================================================
// Reset kernel: zero the sync state (runs before the fused kernel each call).
// ============================================================================
__global__ void reset_kernel() {
    int i = blockIdx.x * blockDim.x + threadIdx.x;
    if (i < SEQ) g_step_done[i] = 0;
    if (i == 0) { g_frontier = 0; g_ticket = 0; }
}

// ============================================================================
// Fused kernel. Blocks 0..115: zx producers. Blocks 116..147: rnn consumers.
// ============================================================================
__global__ void __launch_bounds__(128, 1) fused_kernel(
    const float* __restrict__ x, const float* __restrict__ W,
    const float* __restrict__ b, const float* __restrict__ qp,
    const float* __restrict__ h0, const float* __restrict__ c0,
    float* __restrict__ out)
{
    __shared__ ulonglong2 Ws[IN_DIM * 4];     // zx: outputs 0..15 of each d
    __shared__ ulonglong2 Ws_hi[IN_DIM * 4];  // zx: outputs 16..31 of each d
    __shared__ float bias[32];
    __shared__ float xs[ZX_ROWS * 33];        // zx: staged x / z (pad-33)
    __shared__ __align__(16) ulonglong2 Vbuf[4][2][32];  // rnn: per-warp exchange

    const unsigned FULL = 0xffffffffu;
    int tid = threadIdx.x;

    if (blockIdx.x < ZX_BLOCKS) {
        // ==================== ZX PRODUCER ====================
        float* WsF   = (float*)Ws;
        float* WsFhi = (float*)Ws_hi;
        for (int i = tid; i < IN_DIM * 32; i += 128) {
            int d = i >> 5, o = i & 31;
            float w = W[o * D_TOT + d];
            if (o < 16) WsF[d * 16 + o] = w;
            else        WsFhi[d * 16 + (o - 16)] = w;
        }
        if (tid < 32) bias[tid] = b[tid] + qp[tid];
        __syncthreads();

        __shared__ int s_tile;
        for (;;) {
            if (tid == 0) s_tile = atomicAdd(&g_ticket, 1);
            __syncthreads();
            int tile = s_tile;
            if (tile >= N_TILES) break;

            int rowbase = tile * ZX_ROWS;
            const float* xblk = x + (size_t)rowbase * IN_DIM;

            ull acc[16];
#pragma unroll
            for (int i = 0; i < 16; i++) acc[i] = 0ULL;

            for (int t = 0; t < IN_DIM / 32; t++) {
                __syncthreads();
#pragma unroll
                for (int k = 0; k < 8; k++) {
                    int idx = tid + k * 128;
                    int r = idx >> 3, d4 = idx & 7;
                    float4 v = *(const float4*)(xblk + (size_t)r * IN_DIM + t * 32 + d4 * 4);
                    float* dst = xs + r * 33 + d4 * 4;
                    dst[0] = v.x; dst[1] = v.y; dst[2] = v.z; dst[3] = v.w;
                }
                __syncthreads();

                const float* xr = xs + tid * 33;
#pragma unroll
                for (int dd = 0; dd < 32; dd++) {
                    int d = t * 32 + dd;
                    ull xv = dup2(xr[dd]);
                    const ulonglong2* wlo = Ws    + d * 4;
                    const ulonglong2* whi = Ws_hi + d * 4;
#pragma unroll
                    for (int j = 0; j < 4; j++) {
                        ulonglong2 wp = wlo[j];
                        acc[2 * j]     = fma2(xv, wp.x, acc[2 * j]);
                        acc[2 * j + 1] = fma2(xv, wp.y, acc[2 * j + 1]);
                    }
#pragma unroll
                    for (int j = 0; j < 4; j++) {
                        ulonglong2 wp = whi[j];
                        acc[8 + 2 * j]     = fma2(xv, wp.x, acc[8 + 2 * j]);
                        acc[8 + 2 * j + 1] = fma2(xv, wp.y, acc[8 + 2 * j + 1]);
                    }
                }
            }

            // stage z, coalesced store
            __syncthreads();
            {
                float* zrow = xs + tid * 33;
#pragma unroll
                for (int j = 0; j < 16; j++) {
                    float lo, hi; unpack2(acc[j], lo, hi);
                    zrow[2 * j]     = lo + bias[2 * j];
                    zrow[2 * j + 1] = hi + bias[2 * j + 1];
                }
            }
            __syncthreads();
#pragma unroll
            for (int k = 0; k < 8; k++) {
                int idx = tid + k * 128;
                int r = idx >> 3, d4 = idx & 7;
                const float* src = xs + r * 33 + d4 * 4;
                float4 v = make_float4(src[0], src[1], src[2], src[3]);
                *(float4*)(g_zx + (size_t)(rowbase + r) * 32 + d4 * 4) = v;
            }

            // publish: fence, barrier, one atomic; advance frontier over done steps
            __threadfence();
            __syncthreads();
            if (tid == 0) {
                int s = tile >> 2;
                int old = atomicAdd(&g_step_done[s], 1);
                if (old == 3) {
                    int f = ld_acquire(&g_frontier);
                    while (f < SEQ && ld_acquire(&g_step_done[f]) == 4) {
                        int prev = atomicCAS(&g_frontier, f, f + 1);
                        f = (prev == f) ? f + 1 : prev;
                    }
                }
            }
        }
        return;
    }

    // ==================== RNN CONSUMER ====================
    int lane = tid & 31;
    int warp = tid >> 5;
    int hf = lane & 1;
    int g  = (lane >> 1) & 3;
    int bl = lane >> 3;
    int bb = (blockIdx.x - ZX_BLOCKS) * 16 + warp * 4 + bl;   // batch 0..511
    bool owner = (g == 0);

    int sw  = bl * 8 + hf * 4 + (g ^ bl);
    int srb = bl * 8 + hf * 4;

    ull Wp[4][4];
#pragma unroll
    for (int r = 0; r < 4; r++) {
        const float* wr = W + (g * 8 + 4 * hf + r) * D_TOT + IN_DIM;
#pragma unroll
        for (int k = 0; k < 4; k++) {
            int qb = (k < 2) ? (4 * hf + 2 * k) : (4 * (1 - hf) + 2 * (k - 2));
            Wp[r][k] = pack2(wr[qb], wr[qb + 1]);
        }
    }

    ull hp[4];
    hp[0] = pack2(h0[bb * 8 + 4 * hf],           h0[bb * 8 + 4 * hf + 1]);
    hp[1] = pack2(h0[bb * 8 + 4 * hf + 2],       h0[bb * 8 + 4 * hf + 3]);
    hp[2] = pack2(h0[bb * 8 + 4 * (1 - hf)],     h0[bb * 8 + 4 * (1 - hf) + 1]);
    hp[3] = pack2(h0[bb * 8 + 4 * (1 - hf) + 2], h0[bb * 8 + 4 * (1 - hf) + 3]);

    float4 cv = *(const float4*)(c0 + bb * 8 + 4 * hf);
    ull Cp0 = pack2(cv.x, cv.y);
    ull Cp1 = pack2(cv.z, cv.w);

    bool is_g = (g == 2);
    ull P0  = dup2(is_g ? 105.0f : 26.25f);
    ull P1  = dup2(is_g ? 10.0f  : 0.625f);
    ull Q1  = dup2(is_g ? 45.0f  : 11.25f);
    ull Q2  = dup2(is_g ? 1.0f   : 0.0625f);
    ull ob2 = dup2(is_g ? 0.0f   : 0.5f);
    const ull C105 = dup2(105.0f), C945 = dup2(945.0f);
    const ull C15  = dup2(15.0f),  C420 = dup2(420.0f);

    const float4* zp = (const float4*)g_zx + ((size_t)bb * 8 + g * 2 + hf);
    const size_t Z4STRIDE = (size_t)BATCH * 8;

    // single startup wait: steps 0..7 produced (preload 0..3, first body uses <=7)
    int hw = ld_acquire(&g_frontier);
    while (hw < 8) hw = ld_acquire(&g_frontier);

    float4 zb[4];
#pragma unroll
    for (int u = 0; u < 4; u++) zb[u] = zp[(size_t)u * Z4STRIDE];

    float4* op4 = (float4*)(out + (size_t)bb * 8 + 4 * hf);
    const size_t O4STRIDE = (size_t)BATCH * 2;

    ull H0 = 0ULL, H1 = 0ULL;

    for (int s = 0; s < SEQ; s += 4) {
        // ONE wait per 4 steps, hoisted OUT of the unrolled body:
        // body prefetches steps s+4..s+7 (clamped), so need frontier >= s+8.
        int need = (s + 8 <= SEQ) ? (s + 8) : SEQ;
        if (hw < need) {
            hw = ld_acquire(&g_frontier);
            while (hw < need) hw = ld_acquire(&g_frontier);
        }
#pragma unroll
        for (int u = 0; u < 4; u++) {
            int sp = s + u + 4; sp = sp < SEQ ? sp : SEQ - 1;
            float4 zn = zp[(size_t)sp * Z4STRIDE];

            // dot per row
            ull ac0 = mul2(hp[0], Wp[0][0]);
            ull ac1 = mul2(hp[0], Wp[1][0]);
            ull ac2 = mul2(hp[0], Wp[2][0]);
            ull ac3 = mul2(hp[0], Wp[3][0]);
#pragma unroll
            for (int k = 1; k < 4; k++) {
                ac0 = fma2(hp[k], Wp[0][k], ac0);
                ac1 = fma2(hp[k], Wp[1][k], ac1);
                ac2 = fma2(hp[k], Wp[2][k], ac2);
                ac3 = fma2(hp[k], Wp[3][k], ac3);
            }
            float l0, l1, l2, l3, r0, r1, r2, r3;
            unpack2(ac0, l0, r0); unpack2(ac1, l1, r1);
            unpack2(ac2, l2, r2); unpack2(ac3, l3, r3);
            float a0 = __cosf(zb[u].x + l0 + r0);
            float a1 = __cosf(zb[u].y + l1 + r1);
            float a2 = __cosf(zb[u].z + l2 + r2);
            float a3 = __cosf(zb[u].w + l3 + r3);

            // local cumprod of 4 + cross-half prefix
            float k1 = a0 * a1;
            float t23 = a2 * a3;
            float k2 = k1 * a2;
            float k3 = k1 * t23;
            float T = __shfl_xor_sync(FULL, k3, 1);
            ull M = dup2(hf ? T : 1.0f);
            ull X0 = mul2(M, pack2(a0, k1));
            ull X1 = mul2(M, pack2(k2, k3));

            // gate rational
            ull T0 = mul2(X0, X0), T1 = mul2(X1, X1);
            ull N0 = mul2(X0, fma2(P1, T0, P0));
            ull N1 = mul2(X1, fma2(P1, T1, P0));
            ull B0 = fma2(fma2(Q2, T0, Q1), T0, C105);
            ull B1 = fma2(fma2(Q2, T1, Q1), T1, C105);
            float d0, d1, d2, d3, n0, n1, n2, n3;
            unpack2(B0, d0, d1); unpack2(B1, d2, d3);
            unpack2(N0, n0, n1); unpack2(N1, n2, n3);
            float inv0 = rcp_fast(d0 * d1);
            float inv1 = rcp_fast(d2 * d3);
            ull V0 = fma2(pack2(n0 * d1, n1 * d0), dup2(inv0), ob2);
            ull V1 = fma2(pack2(n2 * d3, n3 * d2), dup2(inv1), ob2);

            // smem gate exchange (per-warp buffer, double-buffered)
            ulonglong2* buf = Vbuf[warp][u & 1];
            ulonglong2 vpk; vpk.x = V0; vpk.y = V1;
            buf[sw] = vpk;
            __syncwarp(FULL);
            ulonglong2 Fv = buf[srb + (0 ^ bl)];
            ulonglong2 Iv = buf[srb + (1 ^ bl)];
            ulonglong2 Gv = buf[srb + (2 ^ bl)];
            ulonglong2 Ov = buf[srb + (3 ^ bl)];

            // cell update + cell tanh
            Cp0 = fma2(Fv.x, Cp0, mul2(Iv.x, Gv.x));
            Cp1 = fma2(Fv.y, Cp1, mul2(Iv.y, Gv.y));
            ull TC0 = mul2(Cp0, Cp0), TC1 = mul2(Cp1, Cp1);
            ull NC0 = mul2(Cp0, fma2(add2(TC0, C105), TC0, C945));
            ull NC1 = mul2(Cp1, fma2(add2(TC1, C105), TC1, C945));
            ull BC0 = fma2(fma2(C15, TC0, C420), TC0, C945);
            ull BC1 = fma2(fma2(C15, TC1, C420), TC1, C945);
            float e0, e1, e2, e3, m0, m1, m2, m3;
            unpack2(BC0, e0, e1); unpack2(BC1, e2, e3);
            unpack2(NC0, m0, m1); unpack2(NC1, m2, m3);
            float iv0 = rcp_fast(e0 * e1);
            float iv1 = rcp_fast(e2 * e3);
            ull TH0 = mul2(pack2(m0 * e1, m1 * e0), dup2(iv0));
            ull TH1 = mul2(pack2(m2 * e3, m3 * e2), dup2(iv1));

            H0 = mul2(Ov.x, TH0);
            H1 = mul2(Ov.y, TH1);

            // half exchange
            ull Hx0 = __shfl_xor_sync(FULL, H0, 1);
            ull Hx1 = __shfl_xor_sync(FULL, H1, 1);
            hp[0] = H0; hp[1] = H1; hp[2] = Hx0; hp[3] = Hx1;

            if (owner) {
                float x0, x1, x2, x3;
                unpack2(H0, x0, x1); unpack2(H1, x2, x3);
                *op4 = make_float4(x0, x1, x2, x3);
            }
            op4 += O4STRIDE;

            zb[u] = zn;
        }
    }

    size_t base = (size_t)SEQ * BATCH * 8;
    if (owner) {
        float x0, x1, x2, x3, y0, y1, y2, y3;
        unpack2(H0, x0, x1); unpack2(H1, x2, x3);
        unpack2(Cp0, y0, y1); unpack2(Cp1, y2, y3);
        *(float4*)(out + base + (size_t)bb * 8 + 4 * hf) = make_float4(x0, x1, x2, x3);
        *(float4*)(out + base + BATCH * 8 + (size_t)bb * 8 + 4 * hf) = make_float4(y0, y1, y2, y3);
    }
}

extern "C" void kernel_launch(void* const* d_in, const int* in_sizes, int n_in,
                              void* d_out, int out_size) {
    const float* x  = (const float*)d_in[0];   // inputs (512,512,128)
    const float* h0 = (const float*)d_in[1];   // (512,8)
    const float* c0 = (const float*)d_in[2];   // (512,8)
    const float* W  = (const float*)d_in[3];   // (4,8,136)
    const float* b  = (const float*)d_in[4];   // (4,8)
    const float* qp = (const float*)d_in[5];   // (4,8)
    float* out = (float*)d_out;

    reset_kernel<<<2, 256>>>();
    fused_kernel<<<NBLK, 128>>>(x, W, b, qp, h0, c0, out);
}

// round 11
// speedup vs baseline: 1.2881x; 1.2881x over previous
#include <cuda_runtime.h>
#include <cstdint>

#define SEQ    512
#define BATCH  512
#define IN_DIM 128
#define NQ     8
#define D_TOT  136   // IN_DIM + NQ

// Scratch: Zx[s][b][o], o = g*8 + q
__device__ float g_zx[(size_t)SEQ * BATCH * 32];

typedef unsigned long long ull;

// --- packed fp32x2 ops (Blackwell; PTX-only) ---
__device__ __forceinline__ ull fma2(ull a, ull b, ull c) {
    ull d; asm("fma.rn.f32x2 %0, %1, %2, %3;" : "=l"(d) : "l"(a), "l"(b), "l"(c)); return d;
}
__device__ __forceinline__ ull mul2(ull a, ull b) {
    ull d; asm("mul.rn.f32x2 %0, %1, %2;" : "=l"(d) : "l"(a), "l"(b)); return d;
}
__device__ __forceinline__ ull add2(ull a, ull b) {
    ull d; asm("add.rn.f32x2 %0, %1, %2;" : "=l"(d) : "l"(a), "l"(b)); return d;
}
__device__ __forceinline__ ull pack2(float lo, float hi) {
    ull d; asm("mov.b64 %0, {%1, %2};" : "=l"(d) : "r"(__float_as_uint(lo)), "r"(__float_as_uint(hi))); return d;
}
__device__ __forceinline__ void unpack2(ull v, float& lo, float& hi) {
    unsigned a, b; asm("mov.b64 {%0, %1}, %2;" : "=r"(a), "=r"(b) : "l"(v));
    lo = __uint_as_float(a); hi = __uint_as_float(b);
}
__device__ __forceinline__ ull dup2(float x) {
    ull d; unsigned u = __float_as_uint(x);
    asm("mov.b64 %0, {%1, %1};" : "=l"(d) : "r"(u)); return d;
}
__device__ __forceinline__ float rcp_fast(float x) {
    float r; asm("rcp.approx.f32 %0, %1;" : "=f"(r) : "f"(x)); return r;
}

// ============================================================================
// Kernel 1: Zx[row][o] = sum_d x[row][d] * W[o][d] + b[o] + qp[o]
//   256 rows/block, 2 rows/thread; d tiled by 16; x staged TRANSPOSED in
//   smem (xs[d][row], pad 259 => conflict-free STS scatter and LDS reads;
//   staging LDGs coalesced). W broadcast-LDS amortized over 2 rows.
// ============================================================================
#define ZX_ROWS 256
#define ZX_DT   16
#define XS_PAD  259

__global__ __launch_bounds__(128) void zx_kernel(
    const float* __restrict__ x, const float* __restrict__ W,
    const float* __restrict__ b, const float* __restrict__ qp)
{
    __shared__ ulonglong2 Ws[IN_DIM * 4];     // outputs 0..15 of each d (8KB)
    __shared__ ulonglong2 Ws_hi[IN_DIM * 4];  // outputs 16..31 of each d (8KB)
    __shared__ float bias[32];
    __shared__ float xs[ZX_DT * XS_PAD];      // transposed x tile (16.6KB)

    int tid = threadIdx.x;
    float* WsF   = (float*)Ws;
    float* WsFhi = (float*)Ws_hi;
    for (int i = tid; i < IN_DIM * 32; i += 128) {
        int d = i >> 5, o = i & 31;
        float w = W[o * D_TOT + d];
        if (o < 16) WsF[d * 16 + o] = w;
        else        WsFhi[d * 16 + (o - 16)] = w;
    }
    if (tid < 32) bias[tid] = b[tid] + qp[tid];

    int rowbase = blockIdx.x * ZX_ROWS;
    const float* xblk = x + (size_t)rowbase * IN_DIM;

    ull acc0[16], acc1[16];
#pragma unroll
    for (int i = 0; i < 16; i++) { acc0[i] = 0ULL; acc1[i] = 0ULL; }

    for (int t = 0; t < IN_DIM / ZX_DT; t++) {
        __syncthreads();   // covers W staging (t=0) and xs reuse (t>0)
        // stage 256 rows x 16 d, transposed. 8 iters: coalesced LDG.128,
        // scatter STS (banks: 3*(4dq+j)+row distinct across warp).
#pragma unroll
        for (int it = 0; it < 8; it++) {
            int idx = it * 128 + tid;
            int r = idx >> 2, dq = idx & 3;
            float4 v = *(const float4*)(xblk + (size_t)r * IN_DIM + t * ZX_DT + dq * 4);
            xs[(dq * 4 + 0) * XS_PAD + r] = v.x;
            xs[(dq * 4 + 1) * XS_PAD + r] = v.y;
            xs[(dq * 4 + 2) * XS_PAD + r] = v.z;
            xs[(dq * 4 + 3) * XS_PAD + r] = v.w;
        }
        __syncthreads();

#pragma unroll
        for (int dd = 0; dd < ZX_DT; dd++) {
            int d = t * ZX_DT + dd;
            ull xa = dup2(xs[dd * XS_PAD + tid]);
            ull xb = dup2(xs[dd * XS_PAD + tid + 128]);
            const ulonglong2* wlo = Ws    + d * 4;
            const ulonglong2* whi = Ws_hi + d * 4;
#pragma unroll
            for (int j = 0; j < 4; j++) {
                ulonglong2 wp = wlo[j];
                acc0[2 * j]     = fma2(xa, wp.x, acc0[2 * j]);
                acc0[2 * j + 1] = fma2(xa, wp.y, acc0[2 * j + 1]);
                acc1[2 * j]     = fma2(xb, wp.x, acc1[2 * j]);
                acc1[2 * j + 1] = fma2(xb, wp.y, acc1[2 * j + 1]);
            }
#pragma unroll
            for (int j = 0; j < 4; j++) {
                ulonglong2 wp = whi[j];
                acc0[8 + 2 * j]     = fma2(xa, wp.x, acc0[8 + 2 * j]);
                acc0[8 + 2 * j + 1] = fma2(xa, wp.y, acc0[8 + 2 * j + 1]);
                acc1[8 + 2 * j]     = fma2(xb, wp.x, acc1[8 + 2 * j]);
                acc1[8 + 2 * j + 1] = fma2(xb, wp.y, acc1[8 + 2 * j + 1]);
            }
        }
    }

    // direct stores (rows tid and tid+128)
    float4* zr0 = (float4*)(g_zx + (size_t)(rowbase + tid) * 32);
    float4* zr1 = (float4*)(g_zx + (size_t)(rowbase + tid + 128) * 32);
#pragma unroll
    for (int j = 0; j < 8; j++) {
        float e0, e1, e2, e3;
        unpack2(acc0[2 * j], e0, e1); unpack2(acc0[2 * j + 1], e2, e3);
        zr0[j] = make_float4(e0 + bias[4 * j], e1 + bias[4 * j + 1],
                             e2 + bias[4 * j + 2], e3 + bias[4 * j + 3]);
        unpack2(acc1[2 * j], e0, e1); unpack2(acc1[2 * j + 1], e2, e3);
        zr1[j] = make_float4(e0 + bias[4 * j], e1 + bias[4 * j + 1],
                             e2 + bias[4 * j + 2], e3 + bias[4 * j + 3]);
    }
}

// ============================================================================
// Kernel 2: recurrence (round-8 structure). 8 lanes/batch, 4 batches/warp,
//   1 warp/block, 128 blocks. smem gate exchange, clamp-free main loop with
//   incremental prefetch pointer + peeled final 4 steps.
// ============================================================================
__global__ void __launch_bounds__(32, 1) rnn_kernel(
    const float* __restrict__ W, const float* __restrict__ h0,
    const float* __restrict__ c0, float* __restrict__ out)
{
    __shared__ __align__(16) ulonglong2 Vbuf[2][32];   // double-buffered

    const unsigned FULL = 0xffffffffu;
    int lane = threadIdx.x;
    int hf = lane & 1;
    int g  = (lane >> 1) & 3;
    int bl = lane >> 3;                       // batch within warp 0..3
    int b  = blockIdx.x * 4 + bl;             // batch 0..511
    bool owner = (g == 0);

    int sw  = bl * 8 + hf * 4 + (g ^ bl);     // swizzled write slot
    int srb = bl * 8 + hf * 4;                // read base; gate G at + (G^bl)

    // Wp[r][k]: W row (g*8 + 4*hf + r), col 128 + qpair. k=0,1 my half; k=2,3 other.
    ull Wp[4][4];
#pragma unroll
    for (int r = 0; r < 4; r++) {
        const float* wr = W + (g * 8 + 4 * hf + r) * D_TOT + IN_DIM;
#pragma unroll
        for (int k = 0; k < 4; k++) {
            int qb = (k < 2) ? (4 * hf + 2 * k) : (4 * (1 - hf) + 2 * (k - 2));
            Wp[r][k] = pack2(wr[qb], wr[qb + 1]);
        }
    }

    ull hp[4];
    hp[0] = pack2(h0[b * 8 + 4 * hf],           h0[b * 8 + 4 * hf + 1]);
    hp[1] = pack2(h0[b * 8 + 4 * hf + 2],       h0[b * 8 + 4 * hf + 3]);
    hp[2] = pack2(h0[b * 8 + 4 * (1 - hf)],     h0[b * 8 + 4 * (1 - hf) + 1]);
    hp[3] = pack2(h0[b * 8 + 4 * (1 - hf) + 2], h0[b * 8 + 4 * (1 - hf) + 3]);

    float4 cv = *(const float4*)(c0 + b * 8 + 4 * hf);
    ull Cp0 = pack2(cv.x, cv.y);
    ull Cp1 = pack2(cv.z, cv.w);

    bool is_g = (g == 2);
    ull P0  = dup2(is_g ? 105.0f : 26.25f);
    ull P1  = dup2(is_g ? 10.0f  : 0.625f);
    ull Q1  = dup2(is_g ? 45.0f  : 11.25f);
    ull Q2  = dup2(is_g ? 1.0f   : 0.0625f);
    ull ob2 = dup2(is_g ? 0.0f   : 0.5f);
    const ull C105 = dup2(105.0f), C945 = dup2(945.0f);
    const ull C15  = dup2(15.0f),  C420 = dup2(420.0f);

    const float4* zp = (const float4*)g_zx + ((size_t)b * 8 + g * 2 + hf);
    const size_t Z4STRIDE = (size_t)BATCH * 8;

    float4 zb[4];
#pragma unroll
    for (int u = 0; u < 4; u++) zb[u] = zp[(size_t)u * Z4STRIDE];
    const float4* pf = zp + 4 * Z4STRIDE;      // incremental prefetch pointer

    float4* op4 = (float4*)(out + (size_t)b * 8 + 4 * hf);
    const size_t O4STRIDE = (size_t)BATCH * 2;

    ull H0 = 0ULL, H1 = 0ULL;

    // one full step; zc is the current step's zx packet
    auto step = [&](float4 zc, ulonglong2* buf) {
        // dot per row
        ull ac0 = mul2(hp[0], Wp[0][0]);
        ull ac1 = mul2(hp[0], Wp[1][0]);
        ull ac2 = mul2(hp[0], Wp[2][0]);
        ull ac3 = mul2(hp[0], Wp[3][0]);
#pragma unroll
        for (int k = 1; k < 4; k++) {
            ac0 = fma2(hp[k], Wp[0][k], ac0);
            ac1 = fma2(hp[k], Wp[1][k], ac1);
            ac2 = fma2(hp[k], Wp[2][k], ac2);
            ac3 = fma2(hp[k], Wp[3][k], ac3);
        }
        float l0, l1, l2, l3, r0, r1, r2, r3;
        unpack2(ac0, l0, r0); unpack2(ac1, l1, r1);
        unpack2(ac2, l2, r2); unpack2(ac3, l3, r3);
        float a0 = __cosf(zc.x + l0 + r0);
        float a1 = __cosf(zc.y + l1 + r1);
        float a2 = __cosf(zc.z + l2 + r2);
        float a3 = __cosf(zc.w + l3 + r3);

        // local cumprod of 4 + cross-half prefix
        float k1 = a0 * a1;
        float t23 = a2 * a3;
        float k2 = k1 * a2;
        float k3 = k1 * t23;
        float T = __shfl_xor_sync(FULL, k3, 1);
        ull M = dup2(hf ? T : 1.0f);
        ull X0 = mul2(M, pack2(a0, k1));
        ull X1 = mul2(M, pack2(k2, k3));

        // gate rational: v = ob + x(P0+P1 t)/(105+Q1 t+Q2 t^2)
        ull T0 = mul2(X0, X0), T1 = mul2(X1, X1);
        ull N0 = mul2(X0, fma2(P1, T0, P0));
        ull N1 = mul2(X1, fma2(P1, T1, P0));
        ull B0 = fma2(fma2(Q2, T0, Q1), T0, C105);
        ull B1 = fma2(fma2(Q2, T1, Q1), T1, C105);
        float d0, d1, d2, d3, n0, n1, n2, n3;
        unpack2(B0, d0, d1); unpack2(B1, d2, d3);
        unpack2(N0, n0, n1); unpack2(N1, n2, n3);
        float inv0 = rcp_fast(d0 * d1);
        float inv1 = rcp_fast(d2 * d3);
        ull V0 = fma2(pack2(n0 * d1, n1 * d0), dup2(inv0), ob2);
        ull V1 = fma2(pack2(n2 * d3, n3 * d2), dup2(inv1), ob2);

        // ONE smem exchange: all 4 gates for my (bl,hf) half
        ulonglong2 vpk; vpk.x = V0; vpk.y = V1;
        buf[sw] = vpk;
        __syncwarp(FULL);
        ulonglong2 Fv = buf[srb + (0 ^ bl)];
        ulonglong2 Iv = buf[srb + (1 ^ bl)];
        ulonglong2 Gv = buf[srb + (2 ^ bl)];
        ulonglong2 Ov = buf[srb + (3 ^ bl)];

        // cell update + cell tanh (redundant on all gate lanes)
        Cp0 = fma2(Fv.x, Cp0, mul2(Iv.x, Gv.x));
        Cp1 = fma2(Fv.y, Cp1, mul2(Iv.y, Gv.y));
        ull TC0 = mul2(Cp0, Cp0), TC1 = mul2(Cp1, Cp1);
        ull NC0 = mul2(Cp0, fma2(add2(TC0, C105), TC0, C945));
        ull NC1 = mul2(Cp1, fma2(add2(TC1, C105), TC1, C945));
        ull BC0 = fma2(fma2(C15, TC0, C420), TC0, C945);
        ull BC1 = fma2(fma2(C15, TC1, C420), TC1, C945);
        float e0, e1, e2, e3, m0, m1, m2, m3;
        unpack2(BC0, e0, e1); unpack2(BC1, e2, e3);
        unpack2(NC0, m0, m1); unpack2(NC1, m2, m3);
        float iv0 = rcp_fast(e0 * e1);
        float iv1 = rcp_fast(e2 * e3);
        ull TH0 = mul2(pack2(m0 * e1, m1 * e0), dup2(iv0));
        ull TH1 = mul2(pack2(m2 * e3, m3 * e2), dup2(iv1));

        H0 = mul2(Ov.x, TH0);
        H1 = mul2(Ov.y, TH1);

        // half exchange: 2 parallel shuffles straight into permuted order
        ull Hx0 = __shfl_xor_sync(FULL, H0, 1);
        ull Hx1 = __shfl_xor_sync(FULL, H1, 1);
        hp[0] = H0; hp[1] = H1; hp[2] = Hx0; hp[3] = Hx1;

        if (owner) {
            float x0, x1, x2, x3;
            unpack2(H0, x0, x1); unpack2(H1, x2, x3);
            *op4 = make_float4(x0, x1, x2, x3);
        }
        op4 += O4STRIDE;
    };

    // main loop: steps 0..507, prefetch 4..511 — no clamp, pure ptr increment
    for (int s = 0; s <= SEQ - 8; s += 4) {
#pragma unroll
        for (int u = 0; u < 4; u++) {
            float4 zn = *pf; pf += Z4STRIDE;
            step(zb[u], Vbuf[u & 1]);
            zb[u] = zn;
        }
    }
    // peeled final 4 steps (508..511), no prefetch
#pragma unroll
    for (int u = 0; u < 4; u++)
        step(zb[u], Vbuf[u & 1]);

    // Final states: h_f then c_f (g0 lanes, each owns q-half hf)
    size_t base = (size_t)SEQ * BATCH * 8;
    if (owner) {
        float x0, x1, x2, x3, y0, y1, y2, y3;
        unpack2(H0, x0, x1); unpack2(H1, x2, x3);
        unpack2(Cp0, y0, y1); unpack2(Cp1, y2, y3);
        *(float4*)(out + base + (size_t)b * 8 + 4 * hf) = make_float4(x0, x1, x2, x3);
        *(float4*)(out + base + BATCH * 8 + (size_t)b * 8 + 4 * hf) = make_float4(y0, y1, y2, y3);
    }
}

extern "C" void kernel_launch(void* const* d_in, const int* in_sizes, int n_in,
                              void* d_out, int out_size) {
    const float* x  = (const float*)d_in[0];   // inputs (512,512,128)
    const float* h0 = (const float*)d_in[1];   // (512,8)
    const float* c0 = (const float*)d_in[2];   // (512,8)
    const float* W  = (const float*)d_in[3];   // (4,8,136)
    const float* b  = (const float*)d_in[4];   // (4,8)
    const float* qp = (const float*)d_in[5];   // (4,8)
    float* out = (float*)d_out;

    zx_kernel<<<(SEQ * BATCH) / ZX_ROWS, 128>>>(x, W, b, qp);
    rnn_kernel<<<BATCH / 4, 32>>>(W, h0, c0, out);
}

// round 12
// speedup vs baseline: 1.3515x; 1.0492x over previous
#include <cuda_runtime.h>
#include <cstdint>

#define SEQ    512
#define BATCH  512
#define IN_DIM 128
#define NQ     8
#define D_TOT  136   // IN_DIM + NQ

// Scratch: Zx[s][b][o], o = g*8 + q
__device__ float g_zx[(size_t)SEQ * BATCH * 32];

typedef unsigned long long ull;

// --- packed fp32x2 ops (Blackwell; PTX-only) ---
__device__ __forceinline__ ull fma2(ull a, ull b, ull c) {
    ull d; asm("fma.rn.f32x2 %0, %1, %2, %3;" : "=l"(d) : "l"(a), "l"(b), "l"(c)); return d;
}
__device__ __forceinline__ ull mul2(ull a, ull b) {
    ull d; asm("mul.rn.f32x2 %0, %1, %2;" : "=l"(d) : "l"(a), "l"(b)); return d;
}
__device__ __forceinline__ ull add2(ull a, ull b) {
    ull d; asm("add.rn.f32x2 %0, %1, %2;" : "=l"(d) : "l"(a), "l"(b)); return d;
}
__device__ __forceinline__ ull pack2(float lo, float hi) {
    ull d; asm("mov.b64 %0, {%1, %2};" : "=l"(d) : "r"(__float_as_uint(lo)), "r"(__float_as_uint(hi))); return d;
}
__device__ __forceinline__ void unpack2(ull v, float& lo, float& hi) {
    unsigned a, b; asm("mov.b64 {%0, %1}, %2;" : "=r"(a), "=r"(b) : "l"(v));
    lo = __uint_as_float(a); hi = __uint_as_float(b);
}
__device__ __forceinline__ ull dup2(float x) {
    ull d; unsigned u = __float_as_uint(x);
    asm("mov.b64 %0, {%1, %1};" : "=l"(d) : "r"(u)); return d;
}
__device__ __forceinline__ float rcp_fast(float x) {
    float r; asm("rcp.approx.f32 %0, %1;" : "=f"(r) : "f"(x)); return r;
}

// ============================================================================
// Kernel 1: Zx[row][o] = sum_d x[row][d] * W[o][d] + b[o] + qp[o]
//   256 rows/block, 2 rows/thread; d tiled by 16; x staged TRANSPOSED
//   (pad 258: staging STS banks 8dq+2j+r' bijective; compute LDS 2dd+tid).
//   Bias folded into acc init. Output staged transposed (pad 130,
//   conflict-free) then stored COALESCED (4 lines/STG.128).
// ============================================================================
#define ZX_ROWS 256
#define XPAD    258
#define ZPAD    130

__global__ __launch_bounds__(128) void zx_kernel(
    const float* __restrict__ x, const float* __restrict__ W,
    const float* __restrict__ b, const float* __restrict__ qp)
{
    __shared__ ulonglong2 Ws[IN_DIM * 4];     // outputs 0..15 of each d (8KB)
    __shared__ ulonglong2 Ws_hi[IN_DIM * 4];  // outputs 16..31 of each d (8KB)
    __shared__ ull bias2[16];
    __shared__ float xs[4160];                // x tile / z staging (16.6KB)

    int tid = threadIdx.x;
    float* WsF   = (float*)Ws;
    float* WsFhi = (float*)Ws_hi;
    for (int i = tid; i < IN_DIM * 32; i += 128) {
        int d = i >> 5, o = i & 31;
        float w = W[o * D_TOT + d];
        if (o < 16) WsF[d * 16 + o] = w;
        else        WsFhi[d * 16 + (o - 16)] = w;
    }
    if (tid < 16) bias2[tid] = pack2(b[2 * tid] + qp[2 * tid],
                                     b[2 * tid + 1] + qp[2 * tid + 1]);
    __syncthreads();

    int rowbase = blockIdx.x * ZX_ROWS;
    const float* xblk = x + (size_t)rowbase * IN_DIM;

    ull acc0[16], acc1[16];
#pragma unroll
    for (int i = 0; i < 16; i++) { acc0[i] = bias2[i]; acc1[i] = bias2[i]; }

    for (int t = 0; t < IN_DIM / 16; t++) {
        if (t) __syncthreads();
        // stage 256 rows x 16 d transposed (coalesced LDG.128, CF STS)
#pragma unroll
        for (int it = 0; it < 8; it++) {
            int idx = it * 128 + tid;
            int r = idx >> 2, dq = idx & 3;
            float4 v = *(const float4*)(xblk + (size_t)r * IN_DIM + t * 16 + dq * 4);
            xs[(dq * 4 + 0) * XPAD + r] = v.x;
            xs[(dq * 4 + 1) * XPAD + r] = v.y;
            xs[(dq * 4 + 2) * XPAD + r] = v.z;
            xs[(dq * 4 + 3) * XPAD + r] = v.w;
        }
        __syncthreads();

#pragma unroll
        for (int dd = 0; dd < 16; dd++) {
            int d = t * 16 + dd;
            ull xa = dup2(xs[dd * XPAD + tid]);
            ull xb = dup2(xs[dd * XPAD + tid + 128]);
            const ulonglong2* wlo = Ws    + d * 4;
            const ulonglong2* whi = Ws_hi + d * 4;
#pragma unroll
            for (int j = 0; j < 4; j++) {
                ulonglong2 wp = wlo[j];
                acc0[2 * j]     = fma2(xa, wp.x, acc0[2 * j]);
                acc0[2 * j + 1] = fma2(xa, wp.y, acc0[2 * j + 1]);
                acc1[2 * j]     = fma2(xb, wp.x, acc1[2 * j]);
                acc1[2 * j + 1] = fma2(xb, wp.y, acc1[2 * j + 1]);
            }
#pragma unroll
            for (int j = 0; j < 4; j++) {
                ulonglong2 wp = whi[j];
                acc0[8 + 2 * j]     = fma2(xa, wp.x, acc0[8 + 2 * j]);
                acc0[8 + 2 * j + 1] = fma2(xa, wp.y, acc0[8 + 2 * j + 1]);
                acc1[8 + 2 * j]     = fma2(xb, wp.x, acc1[8 + 2 * j]);
                acc1[8 + 2 * j + 1] = fma2(xb, wp.y, acc1[8 + 2 * j + 1]);
            }
        }
    }

    // output: stage transposed zs[o*130 + r], then coalesced STG (2 halves)
#pragma unroll
    for (int h = 0; h < 2; h++) {
        __syncthreads();
        const ull* ac = h ? acc1 : acc0;
#pragma unroll
        for (int j = 0; j < 16; j++) {
            float lo, hi; unpack2(ac[j], lo, hi);
            xs[(2 * j) * ZPAD + tid]     = lo;
            xs[(2 * j + 1) * ZPAD + tid] = hi;
        }
        __syncthreads();
        int rb = rowbase + h * 128;
#pragma unroll
        for (int k = 0; k < 8; k++) {
            int idx = k * 128 + tid;
            int r = idx >> 3, d4 = idx & 7;
            float4 v = make_float4(xs[(4 * d4 + 0) * ZPAD + r],
                                   xs[(4 * d4 + 1) * ZPAD + r],
                                   xs[(4 * d4 + 2) * ZPAD + r],
                                   xs[(4 * d4 + 3) * ZPAD + r]);
            *(float4*)(g_zx + (size_t)(rb + r) * 32 + d4 * 4) = v;
        }
    }
}

// ============================================================================
// Kernel 2: recurrence. 8 lanes/batch, 4 batches/warp, 1 warp/block.
//   smem gate exchange; ALL stores unconditional (redundant identical values
//   across the 4 gate lanes of a group -> no BSSY/BSYNC in the loop).
// ============================================================================
__global__ void __launch_bounds__(32, 1) rnn_kernel(
    const float* __restrict__ W, const float* __restrict__ h0,
    const float* __restrict__ c0, float* __restrict__ out)
{
    __shared__ __align__(16) ulonglong2 Vbuf[2][32];   // double-buffered

    const unsigned FULL = 0xffffffffu;
    int lane = threadIdx.x;
    int hf = lane & 1;
    int g  = (lane >> 1) & 3;
    int bl = lane >> 3;                       // batch within warp 0..3
    int b  = blockIdx.x * 4 + bl;             // batch 0..511

    int sw  = bl * 8 + hf * 4 + (g ^ bl);     // swizzled write slot
    int srb = bl * 8 + hf * 4;                // read base; gate G at + (G^bl)

    // Wp[r][k]: W row (g*8 + 4*hf + r), col 128 + qpair. k=0,1 my half; k=2,3 other.
    ull Wp[4][4];
#pragma unroll
    for (int r = 0; r < 4; r++) {
        const float* wr = W + (g * 8 + 4 * hf + r) * D_TOT + IN_DIM;
#pragma unroll
        for (int k = 0; k < 4; k++) {
            int qb = (k < 2) ? (4 * hf + 2 * k) : (4 * (1 - hf) + 2 * (k - 2));
            Wp[r][k] = pack2(wr[qb], wr[qb + 1]);
        }
    }

    ull hp[4];
    hp[0] = pack2(h0[b * 8 + 4 * hf],           h0[b * 8 + 4 * hf + 1]);
    hp[1] = pack2(h0[b * 8 + 4 * hf + 2],       h0[b * 8 + 4 * hf + 3]);
    hp[2] = pack2(h0[b * 8 + 4 * (1 - hf)],     h0[b * 8 + 4 * (1 - hf) + 1]);
    hp[3] = pack2(h0[b * 8 + 4 * (1 - hf) + 2], h0[b * 8 + 4 * (1 - hf) + 3]);

    float4 cv = *(const float4*)(c0 + b * 8 + 4 * hf);
    ull Cp0 = pack2(cv.x, cv.y);
    ull Cp1 = pack2(cv.z, cv.w);

    bool is_g = (g == 2);
    ull P0  = dup2(is_g ? 105.0f : 26.25f);
    ull P1  = dup2(is_g ? 10.0f  : 0.625f);
    ull Q1  = dup2(is_g ? 45.0f  : 11.25f);
    ull Q2  = dup2(is_g ? 1.0f   : 0.0625f);
    ull ob2 = dup2(is_g ? 0.0f   : 0.5f);
    const ull C105 = dup2(105.0f), C945 = dup2(945.0f);
    const ull C15  = dup2(15.0f),  C420 = dup2(420.0f);

    const float4* zp = (const float4*)g_zx + ((size_t)b * 8 + g * 2 + hf);
    const size_t Z4STRIDE = (size_t)BATCH * 8;

    float4 zb[4];
#pragma unroll
    for (int u = 0; u < 4; u++) zb[u] = zp[(size_t)u * Z4STRIDE];
    const float4* pf = zp + 4 * Z4STRIDE;      // incremental prefetch pointer

    float4* op4 = (float4*)(out + (size_t)b * 8 + 4 * hf);
    const size_t O4STRIDE = (size_t)BATCH * 2;

    ull H0 = 0ULL, H1 = 0ULL;

    auto step = [&](float4 zc, ulonglong2* buf) {
        // dot per row
        ull ac0 = mul2(hp[0], Wp[0][0]);
        ull ac1 = mul2(hp[0], Wp[1][0]);
        ull ac2 = mul2(hp[0], Wp[2][0]);
        ull ac3 = mul2(hp[0], Wp[3][0]);
#pragma unroll
        for (int k = 1; k < 4; k++) {
            ac0 = fma2(hp[k], Wp[0][k], ac0);
            ac1 = fma2(hp[k], Wp[1][k], ac1);
            ac2 = fma2(hp[k], Wp[2][k], ac2);
            ac3 = fma2(hp[k], Wp[3][k], ac3);
        }
        float l0, l1, l2, l3, r0, r1, r2, r3;
        unpack2(ac0, l0, r0); unpack2(ac1, l1, r1);
        unpack2(ac2, l2, r2); unpack2(ac3, l3, r3);
        float a0 = __cosf(zc.x + l0 + r0);
        float a1 = __cosf(zc.y + l1 + r1);
        float a2 = __cosf(zc.z + l2 + r2);
        float a3 = __cosf(zc.w + l3 + r3);

        // local cumprod of 4 + cross-half prefix
        float k1 = a0 * a1;
        float t23 = a2 * a3;
        float k2 = k1 * a2;
        float k3 = k1 * t23;
        float T = __shfl_xor_sync(FULL, k3, 1);
        ull M = dup2(hf ? T : 1.0f);
        ull X0 = mul2(M, pack2(a0, k1));
        ull X1 = mul2(M, pack2(k2, k3));

        // gate rational: v = ob + x(P0+P1 t)/(105+Q1 t+Q2 t^2)
        ull T0 = mul2(X0, X0), T1 = mul2(X1, X1);
        ull N0 = mul2(X0, fma2(P1, T0, P0));
        ull N1 = mul2(X1, fma2(P1, T1, P0));
        ull B0 = fma2(fma2(Q2, T0, Q1), T0, C105);
        ull B1 = fma2(fma2(Q2, T1, Q1), T1, C105);
        float d0, d1, d2, d3, n0, n1, n2, n3;
        unpack2(B0, d0, d1); unpack2(B1, d2, d3);
        unpack2(N0, n0, n1); unpack2(N1, n2, n3);
        float inv0 = rcp_fast(d0 * d1);
        float inv1 = rcp_fast(d2 * d3);
        ull V0 = fma2(pack2(n0 * d1, n1 * d0), dup2(inv0), ob2);
        ull V1 = fma2(pack2(n2 * d3, n3 * d2), dup2(inv1), ob2);

        // ONE smem exchange: all 4 gates for my (bl,hf) half
        ulonglong2 vpk; vpk.x = V0; vpk.y = V1;
        buf[sw] = vpk;
        __syncwarp(FULL);
        ulonglong2 Fv = buf[srb + (0 ^ bl)];
        ulonglong2 Iv = buf[srb + (1 ^ bl)];
        ulonglong2 Gv = buf[srb + (2 ^ bl)];
        ulonglong2 Ov = buf[srb + (3 ^ bl)];

        // cell update + cell tanh (identical on all 4 gate lanes)
        Cp0 = fma2(Fv.x, Cp0, mul2(Iv.x, Gv.x));
        Cp1 = fma2(Fv.y, Cp1, mul2(Iv.y, Gv.y));
        ull TC0 = mul2(Cp0, Cp0), TC1 = mul2(Cp1, Cp1);
        ull NC0 = mul2(Cp0, fma2(add2(TC0, C105), TC0, C945));
        ull NC1 = mul2(Cp1, fma2(add2(TC1, C105), TC1, C945));
        ull BC0 = fma2(fma2(C15, TC0, C420), TC0, C945);
        ull BC1 = fma2(fma2(C15, TC1, C420), TC1, C945);
        float e0, e1, e2, e3, m0, m1, m2, m3;
        unpack2(BC0, e0, e1); unpack2(BC1, e2, e3);
        unpack2(NC0, m0, m1); unpack2(NC1, m2, m3);
        float iv0 = rcp_fast(e0 * e1);
        float iv1 = rcp_fast(e2 * e3);
        ull TH0 = mul2(pack2(m0 * e1, m1 * e0), dup2(iv0));
        ull TH1 = mul2(pack2(m2 * e3, m3 * e2), dup2(iv1));

        H0 = mul2(Ov.x, TH0);
        H1 = mul2(Ov.y, TH1);

        // half exchange: 2 parallel shuffles straight into permuted order
        ull Hx0 = __shfl_xor_sync(FULL, H0, 1);
        ull Hx1 = __shfl_xor_sync(FULL, H1, 1);
        hp[0] = H0; hp[1] = H1; hp[2] = Hx0; hp[3] = Hx1;

        // UNCONDITIONAL store: 4 gate lanes write identical value to the
        // same address (no branch -> no BSSY/BSYNC in the loop)
        float x0, x1, x2, x3;
        unpack2(H0, x0, x1); unpack2(H1, x2, x3);
        *op4 = make_float4(x0, x1, x2, x3);
        op4 += O4STRIDE;
    };

    // main loop: steps 0..507, prefetch 4..511 — no clamp, pure ptr increment
    for (int s = 0; s <= SEQ - 8; s += 4) {
#pragma unroll
        for (int u = 0; u < 4; u++) {
            float4 zn = *pf; pf += Z4STRIDE;
            step(zb[u], Vbuf[u & 1]);
            zb[u] = zn;
        }
    }
    // peeled final 4 steps (508..511), no prefetch
#pragma unroll
    for (int u = 0; u < 4; u++)
        step(zb[u], Vbuf[u & 1]);

    // Final states: h_f then c_f (unconditional, redundant identical writes)
    size_t base = (size_t)SEQ * BATCH * 8;
    {
        float x0, x1, x2, x3, y0, y1, y2, y3;
        unpack2(H0, x0, x1); unpack2(H1, x2, x3);
        unpack2(Cp0, y0, y1); unpack2(Cp1, y2, y3);
        *(float4*)(out + base + (size_t)b * 8 + 4 * hf) = make_float4(x0, x1, x2, x3);
        *(float4*)(out + base + BATCH * 8 + (size_t)b * 8 + 4 * hf) = make_float4(y0, y1, y2, y3);
    }
}

extern "C" void kernel_launch(void* const* d_in, const int* in_sizes, int n_in,
                              void* d_out, int out_size) {
    const float* x  = (const float*)d_in[0];   // inputs (512,512,128)
    const float* h0 = (const float*)d_in[1];   // (512,8)
    const float* c0 = (const float*)d_in[2];   // (512,8)
    const float* W  = (const float*)d_in[3];   // (4,8,136)
    const float* b  = (const float*)d_in[4];   // (4,8)
    const float* qp = (const float*)d_in[5];   // (4,8)
    float* out = (float*)d_out;

    zx_kernel<<<(SEQ * BATCH) / ZX_ROWS, 128>>>(x, W, b, qp);
    rnn_kernel<<<BATCH / 4, 32>>>(W, h0, c0, out);
}

// round 13
// speedup vs baseline: 1.3719x; 1.0151x over previous
#include <cuda_runtime.h>
#include <cstdint>

#define SEQ    512
#define BATCH  512
#define IN_DIM 128
#define NQ     8
#define D_TOT  136   // IN_DIM + NQ

// Scratch: Zx[s][b][o], o = g*8 + q
__device__ float g_zx[(size_t)SEQ * BATCH * 32];

typedef unsigned long long ull;

// --- packed fp32x2 ops (Blackwell; PTX-only) ---
__device__ __forceinline__ ull fma2(ull a, ull b, ull c) {
    ull d; asm("fma.rn.f32x2 %0, %1, %2, %3;" : "=l"(d) : "l"(a), "l"(b), "l"(c)); return d;
}
__device__ __forceinline__ ull mul2(ull a, ull b) {
    ull d; asm("mul.rn.f32x2 %0, %1, %2;" : "=l"(d) : "l"(a), "l"(b)); return d;
}
__device__ __forceinline__ ull add2(ull a, ull b) {
    ull d; asm("add.rn.f32x2 %0, %1, %2;" : "=l"(d) : "l"(a), "l"(b)); return d;
}
__device__ __forceinline__ ull pack2(float lo, float hi) {
    ull d; asm("mov.b64 %0, {%1, %2};" : "=l"(d) : "r"(__float_as_uint(lo)), "r"(__float_as_uint(hi))); return d;
}
__device__ __forceinline__ void unpack2(ull v, float& lo, float& hi) {
    unsigned a, b; asm("mov.b64 {%0, %1}, %2;" : "=r"(a), "=r"(b) : "l"(v));
    lo = __uint_as_float(a); hi = __uint_as_float(b);
}
__device__ __forceinline__ ull dup2(float x) {
    ull d; unsigned u = __float_as_uint(x);
    asm("mov.b64 %0, {%1, %1};" : "=l"(d) : "r"(u)); return d;
}
__device__ __forceinline__ float rcp_fast(float x) {
    float r; asm("rcp.approx.f32 %0, %1;" : "=f"(r) : "f"(x)); return r;
}

// ============================================================================
// Kernel 1: Zx[row][o] = sum_d x[row][d] * W[o][d] + b[o] + qp[o]
//   256 rows/block; d tiled by 16; x staged TRANSPOSED (pad 258);
//   W loaded COALESCED into smem then scattered (no strided gmem W reads);
//   output staged transposed (pad 130) then stored coalesced.
// ============================================================================
#define ZX_ROWS 256
#define XPAD    258
#define ZPAD    130

__global__ __launch_bounds__(128) void zx_kernel(
    const float* __restrict__ x, const float* __restrict__ W,
    const float* __restrict__ b, const float* __restrict__ qp)
{
    __shared__ ulonglong2 Ws[IN_DIM * 4];     // outputs 0..15 of each d (8KB)
    __shared__ ulonglong2 Ws_hi[IN_DIM * 4];  // outputs 16..31 of each d (8KB)
    __shared__ ull bias2[16];
    __shared__ float xs[4352];                // W staging / x tile / z staging

    int tid = threadIdx.x;

    // coalesced W load (4,8,136) = 4352 floats = 1088 float4
    for (int i = tid; i < 1088; i += 128)
        ((float4*)xs)[i] = ((const float4*)W)[i];
    if (tid < 16) bias2[tid] = pack2(b[2 * tid] + qp[2 * tid],
                                     b[2 * tid + 1] + qp[2 * tid + 1]);
    __syncthreads();

    float* WsF   = (float*)Ws;
    float* WsFhi = (float*)Ws_hi;
    for (int i = tid; i < IN_DIM * 32; i += 128) {
        int d = i >> 5, o = i & 31;
        float w = xs[o * D_TOT + d];          // from smem, cheap
        if (o < 16) WsF[d * 16 + o] = w;
        else        WsFhi[d * 16 + (o - 16)] = w;
    }

    int rowbase = blockIdx.x * ZX_ROWS;
    const float* xblk = x + (size_t)rowbase * IN_DIM;

    ull acc0[16], acc1[16];
#pragma unroll
    for (int i = 0; i < 16; i++) { acc0[i] = bias2[i]; acc1[i] = bias2[i]; }

    for (int t = 0; t < IN_DIM / 16; t++) {
        __syncthreads();   // protects xs (W scatter reads at t=0, reuse t>0)
#pragma unroll
        for (int it = 0; it < 8; it++) {
            int idx = it * 128 + tid;
            int r = idx >> 2, dq = idx & 3;
            float4 v = *(const float4*)(xblk + (size_t)r * IN_DIM + t * 16 + dq * 4);
            xs[(dq * 4 + 0) * XPAD + r] = v.x;
            xs[(dq * 4 + 1) * XPAD + r] = v.y;
            xs[(dq * 4 + 2) * XPAD + r] = v.z;
            xs[(dq * 4 + 3) * XPAD + r] = v.w;
        }
        __syncthreads();

#pragma unroll
        for (int dd = 0; dd < 16; dd++) {
            int d = t * 16 + dd;
            ull xa = dup2(xs[dd * XPAD + tid]);
            ull xb = dup2(xs[dd * XPAD + tid + 128]);
            const ulonglong2* wlo = Ws    + d * 4;
            const ulonglong2* whi = Ws_hi + d * 4;
#pragma unroll
            for (int j = 0; j < 4; j++) {
                ulonglong2 wp = wlo[j];
                acc0[2 * j]     = fma2(xa, wp.x, acc0[2 * j]);
                acc0[2 * j + 1] = fma2(xa, wp.y, acc0[2 * j + 1]);
                acc1[2 * j]     = fma2(xb, wp.x, acc1[2 * j]);
                acc1[2 * j + 1] = fma2(xb, wp.y, acc1[2 * j + 1]);
            }
#pragma unroll
            for (int j = 0; j < 4; j++) {
                ulonglong2 wp = whi[j];
                acc0[8 + 2 * j]     = fma2(xa, wp.x, acc0[8 + 2 * j]);
                acc0[8 + 2 * j + 1] = fma2(xa, wp.y, acc0[8 + 2 * j + 1]);
                acc1[8 + 2 * j]     = fma2(xb, wp.x, acc1[8 + 2 * j]);
                acc1[8 + 2 * j + 1] = fma2(xb, wp.y, acc1[8 + 2 * j + 1]);
            }
        }
    }

    // output: stage transposed zs[o*130 + r], then coalesced STG (2 halves)
#pragma unroll
    for (int h = 0; h < 2; h++) {
        __syncthreads();
        const ull* ac = h ? acc1 : acc0;
#pragma unroll
        for (int j = 0; j < 16; j++) {
            float lo, hi; unpack2(ac[j], lo, hi);
            xs[(2 * j) * ZPAD + tid]     = lo;
            xs[(2 * j + 1) * ZPAD + tid] = hi;
        }
        __syncthreads();
        int rb = rowbase + h * 128;
#pragma unroll
        for (int k = 0; k < 8; k++) {
            int idx = k * 128 + tid;
            int r = idx >> 3, d4 = idx & 7;
            float4 v = make_float4(xs[(4 * d4 + 0) * ZPAD + r],
                                   xs[(4 * d4 + 1) * ZPAD + r],
                                   xs[(4 * d4 + 2) * ZPAD + r],
                                   xs[(4 * d4 + 3) * ZPAD + r]);
            *(float4*)(g_zx + (size_t)(rb + r) * 32 + d4 * 4) = v;
        }
    }
}

// ============================================================================
// Kernel 2: recurrence. 16 LANES PER BATCH: lane = bl*16 + g*4 + sub.
//   Each lane: ONE q-pair packet of one gate. Single-packet math everywhere.
//   smem gate exchange delivers f,i,g,o to ALL lanes (all lanes fully correct,
//   stores unconditional). h gather: 4 width-4 packet shuffles.
// ============================================================================
__global__ void __launch_bounds__(32, 1) rnn_kernel(
    const float* __restrict__ W, const float* __restrict__ h0,
    const float* __restrict__ c0, float* __restrict__ out)
{
    __shared__ __align__(16) ull Vbuf[2][32];   // double-buffered gate exchange

    const unsigned FULL = 0xffffffffu;
    int lane = threadIdx.x;
    int sub = lane & 3;                  // q-pair index 0..3 (q = 2sub, 2sub+1)
    int g   = (lane >> 2) & 3;           // gate
    int bl  = lane >> 4;                 // batch within warp 0..1
    int b   = blockIdx.x * 2 + bl;       // batch 0..511

    int sw  = bl * 16 + sub * 4 + g;     // write slot (permutation of lanes)
    int srb = bl * 16 + sub * 4;         // read base: 4 consecutive = F,I,G,O

    // Wp[r][k]: W row (g*8 + 2*sub + r), cols 128+2k,129+2k
    ull Wp[2][4];
#pragma unroll
    for (int r = 0; r < 2; r++) {
        const float* wr = W + (g * 8 + 2 * sub + r) * D_TOT + IN_DIM;
#pragma unroll
        for (int k = 0; k < 4; k++)
            Wp[r][k] = pack2(wr[2 * k], wr[2 * k + 1]);
    }

    ull hp[4];
#pragma unroll
    for (int k = 0; k < 4; k++)
        hp[k] = pack2(h0[b * 8 + 2 * k], h0[b * 8 + 2 * k + 1]);

    ull Cp = pack2(c0[b * 8 + 2 * sub], c0[b * 8 + 2 * sub + 1]);

    bool is_g = (g == 2);
    ull P0  = dup2(is_g ? 105.0f : 26.25f);
    ull P1  = dup2(is_g ? 10.0f  : 0.625f);
    ull Q1  = dup2(is_g ? 45.0f  : 11.25f);
    ull Q2  = dup2(is_g ? 1.0f   : 0.0625f);
    ull ob2 = dup2(is_g ? 0.0f   : 0.5f);
    const ull C105 = dup2(105.0f), C945 = dup2(945.0f);
    const ull C15  = dup2(15.0f),  C420 = dup2(420.0f);

    // loop-invariant cumprod predicates
    bool p1 = (sub >= 1), p2 = (sub >= 2), p3 = (sub >= 3);

    // zx: float2 per lane = q-pair (2sub) of gate g
    const float2* zp = (const float2*)g_zx + ((size_t)b * 16 + (lane & 15));
    const size_t Z2STRIDE = (size_t)BATCH * 16;   // float2 per step

    float2 zb[4];
#pragma unroll
    for (int u = 0; u < 4; u++) zb[u] = zp[(size_t)u * Z2STRIDE];
    const float2* pf = zp + 4 * Z2STRIDE;

    float2* op2 = (float2*)out + ((size_t)b * 4 + sub);
    const size_t O2STRIDE = (size_t)BATCH * 4;    // float2 per step

    ull H = 0ULL;

    auto step = [&](float2 zc, ull* buf) {
        // dot: 2 rows, packed over h pairs, horizontal add per row
        ull ac0 = mul2(hp[0], Wp[0][0]);
        ull ac1 = mul2(hp[0], Wp[1][0]);
#pragma unroll
        for (int k = 1; k < 4; k++) {
            ac0 = fma2(hp[k], Wp[0][k], ac0);
            ac1 = fma2(hp[k], Wp[1][k], ac1);
        }
        float l0, r0, l1, r1;
        unpack2(ac0, l0, r0);
        unpack2(ac1, l1, r1);
        float a0 = __cosf(zc.x + l0 + r0);
        float a1 = __cosf(zc.y + l1 + r1);

        // cumprod: local pair + cross-sub prefix (3 parallel width-4 shuffles)
        float k1 = a0 * a1;
        float t0 = __shfl_sync(FULL, k1, 0, 4);
        float t1 = __shfl_sync(FULL, k1, 1, 4);
        float t2 = __shfl_sync(FULL, k1, 2, 4);
        float m = (p1 ? t0 : 1.0f) * ((p2 ? t1 : 1.0f) * (p3 ? t2 : 1.0f));
        ull X = mul2(dup2(m), pack2(a0, k1));

        // gate rational: v = ob + x(P0+P1 t)/(105+Q1 t+Q2 t^2)
        ull T = mul2(X, X);
        ull N = mul2(X, fma2(P1, T, P0));
        ull B = fma2(fma2(Q2, T, Q1), T, C105);
        float d0, d1, n0, n1;
        unpack2(B, d0, d1);
        unpack2(N, n0, n1);
        float inv = rcp_fast(d0 * d1);
        ull V = fma2(pack2(n0 * d1, n1 * d0), dup2(inv), ob2);

        // smem gate exchange: STS.64, sync, 2x LDS.128 -> F,I,G,O
        buf[sw] = V;
        __syncwarp(FULL);
        ulonglong2 FI = *(const ulonglong2*)(buf + srb);
        ulonglong2 GO = *(const ulonglong2*)(buf + srb + 2);

        // cell update + cell tanh (all lanes fully correct)
        Cp = fma2(FI.x, Cp, mul2(FI.y, GO.x));
        ull TC = mul2(Cp, Cp);
        ull NC = mul2(Cp, fma2(add2(TC, C105), TC, C945));
        ull BC = fma2(fma2(C15, TC, C420), TC, C945);
        float e0, e1, m0, m1;
        unpack2(BC, e0, e1);
        unpack2(NC, m0, m1);
        float iv = rcp_fast(e0 * e1);
        ull TH = mul2(pack2(m0 * e1, m1 * e0), dup2(iv));
        H = mul2(GO.y, TH);

        // h gather: packets from sub lanes 0..3 within the quad
        hp[0] = __shfl_sync(FULL, H, 0, 4);
        hp[1] = __shfl_sync(FULL, H, 1, 4);
        hp[2] = __shfl_sync(FULL, H, 2, 4);
        hp[3] = __shfl_sync(FULL, H, 3, 4);

        // unconditional store (4 gate lanes write identical value/address)
        float x0, x1;
        unpack2(H, x0, x1);
        *op2 = make_float2(x0, x1);
        op2 += O2STRIDE;
    };

    // main loop: steps 0..507, prefetch 4..511 — clamp-free ptr increment
    for (int s = 0; s <= SEQ - 8; s += 4) {
#pragma unroll
        for (int u = 0; u < 4; u++) {
            float2 zn = *pf; pf += Z2STRIDE;
            step(zb[u], Vbuf[u & 1]);
            zb[u] = zn;
        }
    }
    // peeled final 4 steps
#pragma unroll
    for (int u = 0; u < 4; u++)
        step(zb[u], Vbuf[u & 1]);

    // Final states: h_f then c_f (unconditional, redundant identical writes)
    size_t base4 = (size_t)SEQ * BATCH * 4;          // in float2 units
    {
        float x0, x1, y0, y1;
        unpack2(H, x0, x1);
        unpack2(Cp, y0, y1);
        ((float2*)out)[base4 + (size_t)b * 4 + sub] = make_float2(x0, x1);
        ((float2*)out)[base4 + BATCH * 4 + (size_t)b * 4 + sub] = make_float2(y0, y1);
    }
}

extern "C" void kernel_launch(void* const* d_in, const int* in_sizes, int n_in,
                              void* d_out, int out_size) {
    const float* x  = (const float*)d_in[0];   // inputs (512,512,128)
    const float* h0 = (const float*)d_in[1];   // (512,8)
    const float* c0 = (const float*)d_in[2];   // (512,8)
    const float* W  = (const float*)d_in[3];   // (4,8,136)
    const float* b  = (const float*)d_in[4];   // (4,8)
    const float* qp = (const float*)d_in[5];   // (4,8)
    float* out = (float*)d_out;

    zx_kernel<<<(SEQ * BATCH) / ZX_ROWS, 128>>>(x, W, b, qp);
    rnn_kernel<<<BATCH / 2, 32>>>(W, h0, c0, out);
}